// round 8
// baseline (speedup 1.0000x reference)
#include <cuda_runtime.h>
#include <cuda_bf16.h>
#include <math.h>

#define NLOC 49104
#define BATCH 16
#define MAXDET 1000
#define CAND 4096
#define NBINS 2048

// Levels: HS = 192,96,48,24,12 ; strides 8,16,32,64,128
// offsets: 0, 36864, 46080, 48384, 48960, 49104

struct Ptrs {
    const float* cls[5];
    const float* reg[5];
    const float* tc[5];
    const float* tr[5];
};

// ------------------------- scratch -------------------------
__device__ unsigned long long g_keys[BATCH * NLOC];        // (flip(m_bits), ~loc)
// stats block (memset to 0 every launch): [coarse hist | refined hist | ccnt]
__device__ unsigned int       g_stats[BATCH * NBINS * 2 + BATCH];
#define G_HIST(b)  (g_stats + (size_t)(b) * NBINS)
#define G_RHIST(b) (g_stats + (size_t)BATCH * NBINS + (size_t)(b) * NBINS)
#define G_CCNT     ((int*)(g_stats + (size_t)BATCH * NBINS * 2))

__device__ int                g_thrc[BATCH];
__device__ int                g_above[BATCH];
__device__ unsigned int       g_Tm[BATCH];
__device__ unsigned long long g_cand[BATCH * CAND];
__device__ float              g_tk_score[BATCH * MAXDET];
__device__ float              g_tk_box[BATCH * MAXDET * 5];
__device__ int                g_tk_cls[BATCH * MAXDET];
__device__ unsigned char      g_tk_valid[BATCH * MAXDET];
__device__ float              g_nms_box[BATCH * MAXDET * 4];
__device__ unsigned long long g_mask[BATCH * MAXDET * 16]; // 2 MB

// ------------------------- helpers -------------------------
__device__ __forceinline__ void loc_to_level(int loc, int& lvl, int& hh, int& local,
                                             int& stride, int& h) {
    if (loc < 36864)      { lvl = 0; hh = 36864; local = loc;         stride = 8;   h = 192; }
    else if (loc < 46080) { lvl = 1; hh = 9216;  local = loc - 36864; stride = 16;  h = 96;  }
    else if (loc < 48384) { lvl = 2; hh = 2304;  local = loc - 46080; stride = 32;  h = 48;  }
    else if (loc < 48960) { lvl = 3; hh = 576;   local = loc - 48384; stride = 64;  h = 24;  }
    else                  { lvl = 4; hh = 144;   local = loc - 48960; stride = 128; h = 12;  }
}

__device__ __forceinline__ unsigned int flip_f32(float f) {
    unsigned int u = __float_as_uint(f);
    return (u & 0x80000000u) ? ~u : (u | 0x80000000u);
}
__device__ __forceinline__ float unflip_f32(unsigned int mk) {
    unsigned int u = (mk & 0x80000000u) ? (mk ^ 0x80000000u) : ~mk;
    return __uint_as_float(u);
}

// decode one selected location into the rank-r output slot
__device__ __forceinline__ void decode_one(const Ptrs& P, int b, int loc, int r,
                                           float score) {
    int t = b * MAXDET + r;
    int lvl, hh, local, stride, h;
    loc_to_level(loc, lvl, hh, local, stride, h);
    int y = local / h;
    int x = local - y * h;
    float cx = (float)(x * stride + stride / 2);
    float cy = (float)(y * stride + stride / 2);

    {
        const float* pc = P.cls[lvl] + (size_t)b * 15 * hh + local;
        float m = pc[0]; int am = 0;
#pragma unroll
        for (int c = 1; c < 15; c++) {
            float v = pc[(size_t)c * hh];
            if (v > m) { m = v; am = c; }
        }
        g_tk_cls[t] = am + 1;
    }

    float theta;
    {
        const float* pt = P.tc[lvl] + (size_t)b * 18 * hh + local;
        float m = pt[0]; int am = 0;
#pragma unroll
        for (int c = 1; c < 18; c++) {
            float v = pt[(size_t)c * hh];
            if (v > m) { m = v; am = c; }
        }
        float trv = P.tr[lvl][(size_t)b * hh + local];
        theta = (float)(am + 1) * 10.0f + trv;
    }

    const float* pr = P.reg[lvl] + (size_t)b * 5 * hh + local;
    float sf = (float)stride;
    float r0 = __fmul_rn(pr[0], sf);
    float r1 = __fmul_rn(pr[(size_t)1 * hh], sf);
    float r2 = __fmul_rn(pr[(size_t)2 * hh], sf);
    float r3 = __fmul_rn(pr[(size_t)3 * hh], sf);
    float x1 = __fsub_rn(cx, r0);
    float y1 = __fsub_rn(cy, r1);
    float x2 = __fadd_rn(cx, r2);
    float y2 = __fadd_rn(cy, r3);

    g_tk_box[t * 5 + 0] = x1;
    g_tk_box[t * 5 + 1] = y1;
    g_tk_box[t * 5 + 2] = x2;
    g_tk_box[t * 5 + 3] = y2;
    g_tk_box[t * 5 + 4] = theta;
    g_nms_box[t * 4 + 0] = x1;
    g_nms_box[t * 4 + 1] = y1;
    g_nms_box[t * 4 + 2] = x2;
    g_nms_box[t * 4 + 3] = y2;
    g_tk_score[t] = score;
    g_tk_valid[t] = (score >= 0.05f) ? 1 : 0;
}

// ------------------------- K1: max logit -> key + coarse hist -------------------------
__global__ void __launch_bounds__(256) k_scores(Ptrs P) {
    __shared__ unsigned int sh[NBINS];
    int tid = threadIdx.x;
    int b = blockIdx.y;
#pragma unroll
    for (int i = tid; i < NBINS; i += 256) sh[i] = 0u;
    __syncthreads();

    int loc = blockIdx.x * 256 + tid;
    if (loc < NLOC) {
        int lvl, hh, local, stride, h;
        loc_to_level(loc, lvl, hh, local, stride, h);
        const float* q = P.cls[lvl] + (size_t)b * 15 * hh + local;
        float m = q[0];
#pragma unroll
        for (int c = 1; c < 15; c++) m = fmaxf(m, q[(size_t)c * hh]);
        unsigned int mk = flip_f32(m);
        g_keys[(size_t)b * NLOC + loc] =
            ((unsigned long long)mk << 32) | (unsigned int)(~(unsigned int)loc);
        atomicAdd(&sh[mk >> 21], 1u);
    }
    __syncthreads();
    unsigned int* gh = G_HIST(b);
#pragma unroll
    for (int i = tid; i < NBINS; i += 256) {
        unsigned int c = sh[i];
        if (c) atomicAdd(&gh[i], c);
    }
}

// ------------------------- K2: coarse threshold -------------------------
__global__ void __launch_bounds__(1024) k_thresh1() {
    __shared__ unsigned int hist[NBINS];
    int b = blockIdx.x;
    int tid = threadIdx.x;
    const unsigned int* gh = G_HIST(b);
    hist[tid] = gh[tid];
    hist[tid + 1024] = gh[tid + 1024];
    __syncthreads();
    for (int off = 1; off < NBINS; off <<= 1) {
        unsigned v0 = hist[tid]        + ((tid + off        < NBINS) ? hist[tid + off]        : 0u);
        unsigned v1 = hist[tid + 1024] + ((tid + 1024 + off < NBINS) ? hist[tid + 1024 + off] : 0u);
        __syncthreads();
        hist[tid] = v0; hist[tid + 1024] = v1;
        __syncthreads();
    }
    for (int i = tid; i < NBINS; i += 1024) {
        unsigned sfx = hist[i];
        unsigned nxt = (i + 1 < NBINS) ? hist[i + 1] : 0u;
        if (sfx >= (unsigned)MAXDET && nxt < (unsigned)MAXDET) {
            g_thrc[b] = i;
            g_above[b] = (int)nxt;
        }
    }
}

// ------------------------- K3: refined hist (full grid) -------------------------
__global__ void __launch_bounds__(256) k_refine() {
    int b = blockIdx.y;
    int loc = blockIdx.x * 256 + threadIdx.x;
    if (loc >= NLOC) return;
    unsigned int thrc = (unsigned int)g_thrc[b];
    unsigned int mk = (unsigned int)(g_keys[(size_t)b * NLOC + loc] >> 32);
    if ((mk >> 21) == thrc) atomicAdd(&G_RHIST(b)[(mk >> 10) & 0x7FFu], 1u);
}

// ------------------------- K4: refined threshold -------------------------
__global__ void __launch_bounds__(1024) k_thresh2() {
    __shared__ unsigned int hist[NBINS];
    __shared__ int s_thrr;
    int b = blockIdx.x;
    int tid = threadIdx.x;
    const unsigned int* gh = G_RHIST(b);
    hist[tid] = gh[tid];
    hist[tid + 1024] = gh[tid + 1024];
    if (tid == 0) s_thrr = 0;
    __syncthreads();
    for (int off = 1; off < NBINS; off <<= 1) {
        unsigned v0 = hist[tid]        + ((tid + off        < NBINS) ? hist[tid + off]        : 0u);
        unsigned v1 = hist[tid + 1024] + ((tid + 1024 + off < NBINS) ? hist[tid + 1024 + off] : 0u);
        __syncthreads();
        hist[tid] = v0; hist[tid + 1024] = v1;
        __syncthreads();
    }
    int extra = MAXDET - g_above[b];  // >= 1
    for (int i = tid; i < NBINS; i += 1024) {
        int sfx = (int)hist[i];
        int nxt = (i + 1 < NBINS) ? (int)hist[i + 1] : 0;
        if (sfx >= extra && nxt < extra) s_thrr = i;
    }
    __syncthreads();
    if (tid == 0) {
        unsigned int T = ((unsigned)g_thrc[b] << 21) | ((unsigned)s_thrr << 10);
        g_Tm[b] = (T >= 4096u) ? (T - 4096u) : 0u;  // tie-safety margin
    }
}

// ------------------------- K5: gather candidates (full grid) -------------------------
__global__ void __launch_bounds__(256) k_gather() {
    int b = blockIdx.y;
    int loc = blockIdx.x * 256 + threadIdx.x;
    if (loc >= NLOC) return;
    unsigned long long k = g_keys[(size_t)b * NLOC + loc];
    if ((unsigned int)(k >> 32) >= g_Tm[b]) {
        int pos = atomicAdd(&G_CCNT[b], 1);
        if (pos < CAND) g_cand[(size_t)b * CAND + pos] = k;
    }
}

// ------------------------- K6: exact sigmoid + rank + decode -------------------------
__global__ void __launch_bounds__(1024) k_rank(Ptrs P) {
    __shared__ unsigned long long sk[CAND];  // 32 KB
    int b = blockIdx.x;
    int tid = threadIdx.x;
    int cnt = min(G_CCNT[b], CAND);

    // exact double-rounded sigmoid for candidates; store (score_bits, ~loc)
    for (int i = tid; i < cnt; i += 1024) {
        unsigned long long k = g_cand[(size_t)b * CAND + i];
        float m = unflip_f32((unsigned int)(k >> 32));
        double s = 1.0 / (1.0 + exp(-(double)m));
        unsigned int bits = __float_as_uint((float)s);
        sk[i] = ((unsigned long long)bits << 32) | (k & 0xFFFFFFFFull);
    }
    __syncthreads();

    // each thread owns up to 4 keys; one broadcast sweep counts strictly-greater keys
    unsigned long long own[4];
    int r[4];
    int nown = 0;
#pragma unroll
    for (int u = 0; u < 4; u++) {
        int i = tid + u * 1024;
        if (i < cnt) { own[u] = sk[i]; r[u] = 0; nown = u + 1; }
    }
    for (int j = 0; j < cnt; j++) {
        unsigned long long kj = sk[j];
#pragma unroll
        for (int u = 0; u < 4; u++)
            if (u < nown) r[u] += (kj > own[u]) ? 1 : 0;
    }
    // fused decode: the owner of each top-1000 key decodes it in place
#pragma unroll
    for (int u = 0; u < 4; u++) {
        if (u < nown && r[u] < MAXDET) {
            unsigned long long k = own[u];
            int loc = (int)(~(unsigned int)(k & 0xFFFFFFFFull));
            float score = __uint_as_float((unsigned int)(k >> 32));
            decode_one(P, b, loc, r[u], score);
        }
    }
}

// ------------------------- K7: tiled IoU mask (64x64 tiles) -------------------------
__global__ void __launch_bounds__(64) k_masks() {
    int jt = blockIdx.x;   // j word (0..15)
    int it = blockIdx.y;   // i tile (0..15)
    int b  = blockIdx.z;
    int tid = threadIdx.x;
    int i = it * 64 + tid;

    if (jt < it) {
        if (i < MAXDET) g_mask[((size_t)b * MAXDET + i) * 16 + jt] = 0ull;
        return;
    }

    __shared__ float jx1[64], jy1[64], jx2[64], jy2[64], ja[64];
    int j0 = jt * 64;
    int lim = min(64, MAXDET - j0);
    if (tid < lim) {
        const float* Bx = g_nms_box + ((size_t)b * MAXDET + j0 + tid) * 4;
        float x1 = Bx[0], y1 = Bx[1], x2 = Bx[2], y2 = Bx[3];
        jx1[tid] = x1; jy1[tid] = y1; jx2[tid] = x2; jy2[tid] = y2;
        ja[tid] = __fmul_rn(fmaxf(__fsub_rn(x2, x1), 0.0f), fmaxf(__fsub_rn(y2, y1), 0.0f));
    }
    __syncthreads();
    if (i >= MAXDET) return;

    const float* Bi = g_nms_box + ((size_t)b * MAXDET + i) * 4;
    float x1i = Bi[0], y1i = Bi[1], x2i = Bi[2], y2i = Bi[3];
    float ai = __fmul_rn(fmaxf(__fsub_rn(x2i, x1i), 0.0f), fmaxf(__fsub_rn(y2i, y1i), 0.0f));

    unsigned long long bits = 0ull;
    int jjstart = (jt == it) ? (tid + 1) : 0;
    for (int jj = jjstart; jj < lim; jj++) {
        float iw = fmaxf(__fsub_rn(fminf(x2i, jx2[jj]), fmaxf(x1i, jx1[jj])), 0.0f);
        float ih = fmaxf(__fsub_rn(fminf(y2i, jy2[jj]), fmaxf(y1i, jy1[jj])), 0.0f);
        float inter = __fmul_rn(iw, ih);
        float un = fmaxf(__fsub_rn(__fadd_rn(ai, ja[jj]), inter), 1e-8f);
        float t = __fmul_rn(0.3f, un);
        bool set;
        if (inter > __fmul_rn(t, 1.000001f))      set = true;
        else if (inter < __fmul_rn(t, 0.999999f)) set = false;
        else set = (__fdiv_rn(inter, un) > 0.3f);  // ambiguous band: exact division
        bits |= ((unsigned long long)set) << jj;
    }
    g_mask[((size_t)b * MAXDET + i) * 16 + jt] = bits;
}

// ------------------------- K8: serial NMS scan + output write -------------------------
__global__ void __launch_bounds__(1024) k_nms(float* __restrict__ out) {
    extern __shared__ unsigned long long sm[];  // 16000 words (125 KB)
    __shared__ unsigned char sval[MAXDET];
    __shared__ unsigned char skeep[MAXDET];

    int b = blockIdx.x;
    int tid = threadIdx.x;

    const ulonglong2* mb2 = (const ulonglong2*)(g_mask + (size_t)b * MAXDET * 16);
    ulonglong2* sm2 = (ulonglong2*)sm;
    for (int i = tid; i < MAXDET * 8; i += 1024) sm2[i] = mb2[i];
    for (int i = tid; i < MAXDET; i += 1024) sval[i] = g_tk_valid[b * MAXDET + i];
    __syncthreads();

    if (tid < 32) {
        unsigned long long rem[16];
#pragma unroll
        for (int u = 0; u < 16; u++) rem[u] = 0ull;

#pragma unroll
        for (int w = 0; w < 16; w++) {
            unsigned long long rw = rem[w];
            int lim = min(64, MAXDET - w * 64);
            for (int bit = 0; bit < lim; bit++) {
                int i = w * 64 + bit;
                bool kept = sval[i] && !((rw >> bit) & 1ull);
                skeep[i] = kept ? 1 : 0;
                if (kept) {
                    const unsigned long long* row = &sm[i * 16];
#pragma unroll
                    for (int u = 0; u < 16; u++) rem[u] |= row[u];
                    rw = rem[w];
                }
            }
        }
    }
    __syncthreads();

    float* out_s = out;
    float* out_c = out + BATCH * MAXDET;
    float* out_b = out + 2 * BATCH * MAXDET;
    for (int i = tid; i < MAXDET; i += 1024) {
        int g = b * MAXDET + i;
        bool k = skeep[i] != 0;
        out_s[g] = k ? g_tk_score[g] : 0.0f;
        out_c[g] = k ? (float)g_tk_cls[g] : 0.0f;
#pragma unroll
        for (int u = 0; u < 5; u++) out_b[(size_t)g * 5 + u] = k ? g_tk_box[g * 5 + u] : 0.0f;
    }
}

// ------------------------- launch -------------------------
extern "C" void kernel_launch(void* const* d_in, const int* in_sizes, int n_in,
                              void* d_out, int out_size) {
    Ptrs P;
    for (int l = 0; l < 5; l++) {
        P.cls[l] = (const float*)d_in[l];
        P.reg[l] = (const float*)d_in[5 + l];
        P.tc[l]  = (const float*)d_in[10 + l];
        P.tr[l]  = (const float*)d_in[15 + l];
    }
    float* out = (float*)d_out;

    cudaFuncSetAttribute(k_nms, cudaFuncAttributeMaxDynamicSharedMemorySize,
                         MAXDET * 16 * (int)sizeof(unsigned long long) + 4096);

    void* stats_ptr = nullptr;
    cudaGetSymbolAddress(&stats_ptr, g_stats);
    cudaMemsetAsync(stats_ptr, 0, sizeof(unsigned int) * (BATCH * NBINS * 2 + BATCH));

    dim3 gridLoc((NLOC + 255) / 256, BATCH);
    k_scores<<<gridLoc, 256>>>(P);
    k_thresh1<<<BATCH, 1024>>>();
    k_refine<<<gridLoc, 256>>>();
    k_thresh2<<<BATCH, 1024>>>();
    k_gather<<<gridLoc, 256>>>();
    k_rank<<<BATCH, 1024>>>(P);
    k_masks<<<dim3(16, 16, BATCH), 64>>>();
    k_nms<<<BATCH, 1024, MAXDET * 16 * (int)sizeof(unsigned long long)>>>(out);

    (void)in_sizes; (void)n_in; (void)out_size;
}